// round 14
// baseline (speedup 1.0000x reference)
#include <cuda_runtime.h>
#include <cuda_fp16.h>
#include <cstdint>

#define Bsz 8
#define Pp  16
#define Dd  512
#define Ee  8192
#define Mm  8192
#define LOG2E 1.4426950408889634f

// Scratch (device globals). Column space is PERMUTED: e' = p*512 + d
// (vs logical e = d*16 + p). W2h/b2p/E/Zpart/Zinv all live in e'-space.
__device__ __half g_Hh[(size_t)Mm * Dd];    // fp16(H), row-major [M][512]
__device__ __half g_W2h[(size_t)Ee * Dd];   // fp16 of (W2*log2e)^T, [e'][512]
__device__ float  g_b2p[Ee];                // b2*log2e, permuted
__device__ __half g_E[(size_t)Mm * Ee];     // exp(relu(logits)), [row][e']
__device__ float g_Zpart[64 * Ee];
__device__ float g_Zinv[Bsz * Ee];

// ======================= PTX helpers =======================
__device__ __forceinline__ uint32_t smem_u32(const void* p) {
    uint32_t a;
    asm("{ .reg .u64 t; cvta.to.shared.u64 t, %1; cvt.u32.u64 %0, t; }" : "=r"(a) : "l"(p));
    return a;
}
#define CP16(dst, src) \
    asm volatile("cp.async.cg.shared.global [%0], [%1], 16;" :: "r"(dst), "l"(src) : "memory")
#define CP_COMMIT() asm volatile("cp.async.commit_group;" ::: "memory")
#define CP_WAIT(n)  asm volatile("cp.async.wait_group %0;" :: "n"(n) : "memory")

__device__ __forceinline__ void ldsm4(uint32_t* r, uint32_t addr) {
    asm volatile("ldmatrix.sync.aligned.m8n8.x4.shared.b16 {%0,%1,%2,%3}, [%4];"
                 : "=r"(r[0]), "=r"(r[1]), "=r"(r[2]), "=r"(r[3]) : "r"(addr));
}
__device__ __forceinline__ void mma16816(float* c, const uint32_t* a, const uint32_t* b) {
    asm volatile("mma.sync.aligned.m16n8k16.row.col.f32.f16.f16.f32 "
                 "{%0,%1,%2,%3}, {%4,%5,%6,%7}, {%8,%9}, {%0,%1,%2,%3};"
                 : "+f"(c[0]), "+f"(c[1]), "+f"(c[2]), "+f"(c[3])
                 : "r"(a[0]), "r"(a[1]), "r"(a[2]), "r"(a[3]), "r"(b[0]), "r"(b[1]));
}
__device__ __forceinline__ float ex2f(float x) {
    float r;
    asm("ex2.approx.ftz.f32 %0, %1;" : "=f"(r) : "f"(x));
    return r;
}

// ======================= K0: fused prep (hidden | W2 permute+convert | b2 permute) ===============
__global__ __launch_bounds__(512) void k_prep(const float* __restrict__ x,
                                              const float* __restrict__ W1,
                                              const float* __restrict__ b1,
                                              const float* __restrict__ W2,
                                              const float* __restrict__ b2) {
    __shared__ float sbuf[8448];
    int tid = threadIdx.x;
    if (blockIdx.x < 512) {
        int row0 = blockIdx.x * 16;
        float* W1s = sbuf;                  // [p][d]
        float* xs  = sbuf + 8192;           // [16][16]
        const float4* W14 = (const float4*)W1;
        float4* W1s4 = (float4*)W1s;
#pragma unroll
        for (int i = 0; i < 4; i++) W1s4[i * 512 + tid] = W14[i * 512 + tid];
        if (tid < 256) xs[tid] = x[row0 * Pp + tid];
        __syncthreads();
        float bb = b1[tid];
#pragma unroll
        for (int r = 0; r < 16; r++) {
            float acc = bb;
#pragma unroll
            for (int p = 0; p < Pp; p++) acc = fmaf(xs[r * Pp + p], W1s[p * Dd + tid], acc);
            g_Hh[(size_t)(row0 + r) * Dd + tid] = __float2half(fmaxf(acc, 0.0f));
        }
    } else {
        int bid = blockIdx.x - 512;         // 0..1023
        int e0 = (bid & 127) * 64, k0 = (bid >> 7) * 64;
        float (*ts)[65] = (float(*)[65])sbuf;
#pragma unroll
        for (int idx = tid; idx < 4096; idx += 512) {
            int i = idx >> 6, j = idx & 63;
            ts[i][j] = W2[(size_t)(k0 + i) * Ee + e0 + j] * LOG2E;
        }
        __syncthreads();
#pragma unroll
        for (int idx = tid; idx < 4096; idx += 512) {
            int j = idx >> 6, i = idx & 63;         // j=e offset, i=k offset
            int e = e0 + j;
            int ep = (e & 15) * Dd + (e >> 4);      // permuted column index
            g_W2h[(size_t)ep * Dd + k0 + i] = __float2half(ts[i][j]);
        }
        if ((bid >> 7) == 0 && tid < 64) {          // once per e-tile: permuted bias
            int e = e0 + tid;
            int ep = (e & 15) * Dd + (e >> 4);
            g_b2p[ep] = b2[e] * LOG2E;
        }
    }
}

// ======================= K2: mma.sync fp16 GEMM + fused epilogue (proven, at HMMA floor) =========
#define TILE_B   10240
#define STAGE_B  20480
#define NSTG     5
#define SMEM_DYN (NSTG * STAGE_B)
#define LDT      40

__global__ __launch_bounds__(256, 2) void k_gemm_mma() {
    extern __shared__ char sm[];
    uint32_t smb = smem_u32(sm);
    int tid = threadIdx.x;
    int wid = tid >> 5, lane = tid & 31;
    int wm = wid >> 2, wn = wid & 3;

    int bid = blockIdx.x;
    int rt = (bid & 511) >> 3;
    int ct = ((bid >> 9) << 3) | (bid & 7);
    int row0 = rt * 128, col0 = ct * 128;

    float c[4][4][4];
#pragma unroll
    for (int i = 0; i < 4; i++)
#pragma unroll
        for (int j = 0; j < 4; j++)
#pragma unroll
            for (int q = 0; q < 4; q++) c[i][j][q] = 0.f;

    auto load_stage = [&](int s, int st) {
        uint32_t sb = smb + st * STAGE_B;
#pragma unroll
        for (int v = 0; v < 2; v++) {
            int f = tid + v * 256;
            int r = f >> 2, cq = f & 3;
            uint32_t soff = r * (LDT * 2) + cq * 16;
            size_t ga = ((size_t)(row0 + r) << 10) + (size_t)s * 64 + cq * 16;
            size_t gb = ((size_t)(col0 + r) << 10) + (size_t)s * 64 + cq * 16;
            CP16(sb + soff,          (const char*)g_Hh  + ga);
            CP16(sb + TILE_B + soff, (const char*)g_W2h + gb);
        }
    };

    load_stage(0, 0); CP_COMMIT();
    load_stage(1, 1); CP_COMMIT();
    load_stage(2, 2); CP_COMMIT();

    int bc = 0, bl = 3;
    for (int s = 0; s < 16; s++) {
        if (s + 3 < 16) {
            load_stage(s + 3, bl); CP_COMMIT();
            if (++bl == NSTG) bl = 0;
        }
        if (s < 13)      CP_WAIT(3);
        else if (s < 14) CP_WAIT(2);
        else if (s < 15) CP_WAIT(1);
        else             CP_WAIT(0);
        __syncthreads();

        uint32_t base = smb + bc * STAGE_B;
        if (++bc == NSTG) bc = 0;
#pragma unroll
        for (int ks = 0; ks < 2; ks++) {
            uint32_t a[4][4], bh[2][4];
            {
                int arow = wm * 64 + (lane & 15);
                int ak = ks * 16 + ((lane >> 4) << 3);
                uint32_t aoff = base + (uint32_t)(arow * (LDT * 2) + ak * 2);
#pragma unroll
                for (int i = 0; i < 4; i++) ldsm4(a[i], aoff + i * 16 * (LDT * 2));
            }
            {
                int g = lane >> 3, r = lane & 7;
                int bn = wn * 32 + ((g >> 1) << 3) + r;
                int bk = ks * 16 + ((g & 1) << 3);
                uint32_t boff = base + TILE_B + (uint32_t)(bn * (LDT * 2) + bk * 2);
#pragma unroll
                for (int j = 0; j < 2; j++)
                    ldsm4(bh[j], boff + j * 16 * (LDT * 2));
            }
#pragma unroll
            for (int i = 0; i < 4; i++)
#pragma unroll
                for (int jj = 0; jj < 4; jj++)
                    mma16816(c[i][jj], a[i], &bh[jj >> 1][(jj & 1) * 2]);
        }
    }
    __syncthreads();

    float* eb = (float*)sm;
    float* red = (float*)(sm + 66560);
#pragma unroll
    for (int i = 0; i < 4; i++) {
#pragma unroll
        for (int jj = 0; jj < 4; jj++) {
            int r = wm * 64 + i * 16 + (lane >> 2);
            int cc = wn * 32 + jj * 8 + (lane & 3) * 2;
            *(float2*)&eb[r * 130 + cc]       = make_float2(c[i][jj][0], c[i][jj][1]);
            *(float2*)&eb[(r + 8) * 130 + cc] = make_float2(c[i][jj][2], c[i][jj][3]);
        }
    }
    __syncthreads();
    {
        int col = tid & 127, half = tid >> 7;
        float bias = g_b2p[col0 + col];
        float csum = 0.f;
        size_t gbase = (size_t)(row0 + half * 64) * Ee + col0 + col;
#pragma unroll 8
        for (int r = 0; r < 64; r++) {
            float v = ex2f(fmaxf(eb[(half * 64 + r) * 130 + col] + bias, 0.0f));
            csum += v;
            g_E[gbase + (size_t)r * Ee] = __float2half(v);
        }
        red[half * 128 + col] = csum;
    }
    __syncthreads();
    if (tid < 128)
        g_Zpart[(size_t)rt * Ee + col0 + tid] = red[tid] + red[128 + tid];
}

// ======================= K2b: softmax denominators (float4) =======================
__global__ void k_zreduce() {
    int idx4 = blockIdx.x * blockDim.x + threadIdx.x;   // 0..16383 (float4 index)
    int b = idx4 >> 11;                                 // 2048 float4 per batch
    int e4 = idx4 & 2047;
    float4 s = make_float4(0.f, 0.f, 0.f, 0.f);
#pragma unroll
    for (int i = 0; i < 8; i++) {
        float4 z = ((const float4*)g_Zpart)[(size_t)(b * 8 + i) * 2048 + e4];
        s.x += z.x; s.y += z.y; s.z += z.z; s.w += z.w;
    }
    ((float4*)g_Zinv)[idx4] = make_float4(1.f / s.x, 1.f / s.y, 1.f / s.z, 1.f / s.w);
}

// ======================= K3: syncless streaming pool (permuted E, 8-wide lanes) =======================
// E row is [p][d] (p = warp, d contiguous). Lane owns 8 consecutive d per chunk,
// 2 chunks of 256. Loads: 2x LDG.128 per row; stores: 4x STG.128. Shuffles for
// run boundaries; zero smem, zero barriers.
#define RPC 2
__global__ __launch_bounds__(512, 3) void k_final(const float* __restrict__ x,
                                                  float* __restrict__ out) {
    const unsigned FULL = 0xFFFFFFFFu;
    int tid = threadIdx.x, w = tid >> 5, lane = tid & 31;
    int b = blockIdx.x >> 9;                 // 512 CTAs per batch
    int row0 = blockIdx.x * RPC;

    float zr[2][8];
    {
        const float* Zb = g_Zinv + (size_t)b * Ee + w * Dd + lane * 8;
#pragma unroll
        for (int c = 0; c < 2; c++) {
            float4 z0 = *(const float4*)(Zb + c * 256);
            float4 z1 = *(const float4*)(Zb + c * 256 + 4);
            zr[c][0] = z0.x; zr[c][1] = z0.y; zr[c][2] = z0.z; zr[c][3] = z0.w;
            zr[c][4] = z1.x; zr[c][5] = z1.y; zr[c][6] = z1.z; zr[c][7] = z1.w;
        }
    }

#pragma unroll
    for (int r = 0; r < RPC; r++) {
        int row = row0 + r;
        float xp = __ldg(&x[row * Pp + w]) * (1.0f / 3.0f);
        const __half* Eb = g_E + (size_t)row * Ee + w * Dd + lane * 8;

        float v[2][8];
#pragma unroll
        for (int c = 0; c < 2; c++) {
            uint4 ee = *(const uint4*)(Eb + c * 256);
            const __half2* hh = (const __half2*)&ee;
#pragma unroll
            for (int q = 0; q < 4; q++) {
                float2 f = __half22float2(hh[q]);
                v[c][q * 2]     = f.x * zr[c][q * 2];
                v[c][q * 2 + 1] = f.y * zr[c][q * 2 + 1];
            }
        }

        // boundary values: left of run (prev lane's v[c][7]), right (next lane's v[c][0])
        float lb[2], rb[2];
#pragma unroll
        for (int c = 0; c < 2; c++) {
            lb[c] = __shfl_up_sync(FULL, v[c][7], 1);
            rb[c] = __shfl_down_sync(FULL, v[c][0], 1);
        }
        float t31_0 = __shfl_sync(FULL, v[0][7], 31);   // d=255 (end of chunk0)
        float t0_1  = __shfl_sync(FULL, v[1][0], 0);    // d=256 (start of chunk1)
        if (lane == 0)  { lb[0] = 0.0f; lb[1] = t31_0; }
        if (lane == 31) { rb[1] = 0.0f; rb[0] = t0_1; }

        size_t ob = ((size_t)row * Pp + w) * Dd + lane * 8;
#pragma unroll
        for (int c = 0; c < 2; c++) {
            float o[8];
            o[0] = xp * (lb[c] + v[c][0] + v[c][1]);
#pragma unroll
            for (int q = 1; q < 7; q++)
                o[q] = xp * (v[c][q - 1] + v[c][q] + v[c][q + 1]);
            o[7] = xp * (v[c][6] + v[c][7] + rb[c]);
            *(float4*)(out + ob + c * 256)     = make_float4(o[0], o[1], o[2], o[3]);
            *(float4*)(out + ob + c * 256 + 4) = make_float4(o[4], o[5], o[6], o[7]);
        }
    }
}

// ======================= launch =======================
extern "C" void kernel_launch(void* const* d_in, const int* in_sizes, int n_in,
                              void* d_out, int out_size) {
    const float* x  = (const float*)d_in[0];
    const float* W1 = (const float*)d_in[1];
    const float* b1 = (const float*)d_in[2];
    const float* W2 = (const float*)d_in[3];
    const float* b2 = (const float*)d_in[4];
    float* out = (float*)d_out;

    static int smem_set = 0;
    if (!smem_set) {
        cudaFuncSetAttribute(k_gemm_mma, cudaFuncAttributeMaxDynamicSharedMemorySize, SMEM_DYN);
        smem_set = 1;
    }

    k_prep<<<1536, 512>>>(x, W1, b1, W2, b2);
    k_gemm_mma<<<4096, 256, SMEM_DYN>>>();
    k_zreduce<<<64, 256>>>();
    k_final<<<Mm / RPC, 512>>>(x, out);
}

// round 15
// speedup vs baseline: 1.5785x; 1.5785x over previous
#include <cuda_runtime.h>
#include <cuda_fp16.h>
#include <cstdint>

#define Bsz 8
#define Pp  16
#define Dd  512
#define Ee  8192
#define Mm  8192
#define LOG2E 1.4426950408889634f

// Scratch (device globals). Column space is PERMUTED: e' = p*512 + d
// (vs logical e = d*16 + p). W2h/b2p/E/Zpart/Zinv all live in e'-space.
__device__ __half g_Hh[(size_t)Mm * Dd];    // fp16(H), row-major [M][512]
__device__ __half g_W2h[(size_t)Ee * Dd];   // fp16 of (W2*log2e)^T, [e'][512]
__device__ float  g_b2p[Ee];                // b2*log2e, permuted
__device__ __half g_E[(size_t)Mm * Ee];     // exp(relu(logits)), [row][e']
__device__ float g_Zpart[64 * Ee];
__device__ float g_Zinv[Bsz * Ee];

// ======================= PTX helpers =======================
__device__ __forceinline__ uint32_t smem_u32(const void* p) {
    uint32_t a;
    asm("{ .reg .u64 t; cvta.to.shared.u64 t, %1; cvt.u32.u64 %0, t; }" : "=r"(a) : "l"(p));
    return a;
}
#define CP16(dst, src) \
    asm volatile("cp.async.cg.shared.global [%0], [%1], 16;" :: "r"(dst), "l"(src) : "memory")
#define CP_COMMIT() asm volatile("cp.async.commit_group;" ::: "memory")
#define CP_WAIT(n)  asm volatile("cp.async.wait_group %0;" :: "n"(n) : "memory")

__device__ __forceinline__ void ldsm4(uint32_t* r, uint32_t addr) {
    asm volatile("ldmatrix.sync.aligned.m8n8.x4.shared.b16 {%0,%1,%2,%3}, [%4];"
                 : "=r"(r[0]), "=r"(r[1]), "=r"(r[2]), "=r"(r[3]) : "r"(addr));
}
__device__ __forceinline__ void mma16816(float* c, const uint32_t* a, const uint32_t* b) {
    asm volatile("mma.sync.aligned.m16n8k16.row.col.f32.f16.f16.f32 "
                 "{%0,%1,%2,%3}, {%4,%5,%6,%7}, {%8,%9}, {%0,%1,%2,%3};"
                 : "+f"(c[0]), "+f"(c[1]), "+f"(c[2]), "+f"(c[3])
                 : "r"(a[0]), "r"(a[1]), "r"(a[2]), "r"(a[3]), "r"(b[0]), "r"(b[1]));
}
__device__ __forceinline__ float ex2f(float x) {
    float r;
    asm("ex2.approx.ftz.f32 %0, %1;" : "=f"(r) : "f"(x));
    return r;
}

// ======================= K0: fused prep (hidden | W2 permute+convert | b2 permute) ===============
__global__ __launch_bounds__(512) void k_prep(const float* __restrict__ x,
                                              const float* __restrict__ W1,
                                              const float* __restrict__ b1,
                                              const float* __restrict__ W2,
                                              const float* __restrict__ b2) {
    __shared__ float sbuf[8448];
    int tid = threadIdx.x;
    if (blockIdx.x < 512) {
        int row0 = blockIdx.x * 16;
        float* W1s = sbuf;                  // [p][d]
        float* xs  = sbuf + 8192;           // [16][16]
        const float4* W14 = (const float4*)W1;
        float4* W1s4 = (float4*)W1s;
#pragma unroll
        for (int i = 0; i < 4; i++) W1s4[i * 512 + tid] = W14[i * 512 + tid];
        if (tid < 256) xs[tid] = x[row0 * Pp + tid];
        __syncthreads();
        float bb = b1[tid];
#pragma unroll
        for (int r = 0; r < 16; r++) {
            float acc = bb;
#pragma unroll
            for (int p = 0; p < Pp; p++) acc = fmaf(xs[r * Pp + p], W1s[p * Dd + tid], acc);
            g_Hh[(size_t)(row0 + r) * Dd + tid] = __float2half(fmaxf(acc, 0.0f));
        }
    } else {
        int bid = blockIdx.x - 512;         // 0..1023
        int e0 = (bid & 127) * 64, k0 = (bid >> 7) * 64;
        float (*ts)[65] = (float(*)[65])sbuf;
#pragma unroll
        for (int idx = tid; idx < 4096; idx += 512) {
            int i = idx >> 6, j = idx & 63;
            ts[i][j] = W2[(size_t)(k0 + i) * Ee + e0 + j] * LOG2E;
        }
        __syncthreads();
#pragma unroll
        for (int idx = tid; idx < 4096; idx += 512) {
            int j = idx >> 6, i = idx & 63;         // j=e offset, i=k offset
            int e = e0 + j;
            int ep = (e & 15) * Dd + (e >> 4);      // permuted column index
            g_W2h[(size_t)ep * Dd + k0 + i] = __float2half(ts[i][j]);
        }
        if ((bid >> 7) == 0 && tid < 64) {          // once per e-tile: permuted bias
            int e = e0 + tid;
            int ep = (e & 15) * Dd + (e >> 4);
            g_b2p[ep] = b2[e] * LOG2E;
        }
    }
}

// ======================= K2: mma.sync fp16 GEMM + fused epilogue (proven, at HMMA floor) =========
#define TILE_B   10240
#define STAGE_B  20480
#define NSTG     5
#define SMEM_DYN (NSTG * STAGE_B)
#define LDT      40

__global__ __launch_bounds__(256, 2) void k_gemm_mma() {
    extern __shared__ char sm[];
    uint32_t smb = smem_u32(sm);
    int tid = threadIdx.x;
    int wid = tid >> 5, lane = tid & 31;
    int wm = wid >> 2, wn = wid & 3;

    int bid = blockIdx.x;
    int rt = (bid & 511) >> 3;
    int ct = ((bid >> 9) << 3) | (bid & 7);
    int row0 = rt * 128, col0 = ct * 128;

    float c[4][4][4];
#pragma unroll
    for (int i = 0; i < 4; i++)
#pragma unroll
        for (int j = 0; j < 4; j++)
#pragma unroll
            for (int q = 0; q < 4; q++) c[i][j][q] = 0.f;

    auto load_stage = [&](int s, int st) {
        uint32_t sb = smb + st * STAGE_B;
#pragma unroll
        for (int v = 0; v < 2; v++) {
            int f = tid + v * 256;
            int r = f >> 2, cq = f & 3;
            uint32_t soff = r * (LDT * 2) + cq * 16;
            size_t ga = ((size_t)(row0 + r) << 10) + (size_t)s * 64 + cq * 16;
            size_t gb = ((size_t)(col0 + r) << 10) + (size_t)s * 64 + cq * 16;
            CP16(sb + soff,          (const char*)g_Hh  + ga);
            CP16(sb + TILE_B + soff, (const char*)g_W2h + gb);
        }
    };

    load_stage(0, 0); CP_COMMIT();
    load_stage(1, 1); CP_COMMIT();
    load_stage(2, 2); CP_COMMIT();

    int bc = 0, bl = 3;
    for (int s = 0; s < 16; s++) {
        if (s + 3 < 16) {
            load_stage(s + 3, bl); CP_COMMIT();
            if (++bl == NSTG) bl = 0;
        }
        if (s < 13)      CP_WAIT(3);
        else if (s < 14) CP_WAIT(2);
        else if (s < 15) CP_WAIT(1);
        else             CP_WAIT(0);
        __syncthreads();

        uint32_t base = smb + bc * STAGE_B;
        if (++bc == NSTG) bc = 0;
#pragma unroll
        for (int ks = 0; ks < 2; ks++) {
            uint32_t a[4][4], bh[2][4];
            {
                int arow = wm * 64 + (lane & 15);
                int ak = ks * 16 + ((lane >> 4) << 3);
                uint32_t aoff = base + (uint32_t)(arow * (LDT * 2) + ak * 2);
#pragma unroll
                for (int i = 0; i < 4; i++) ldsm4(a[i], aoff + i * 16 * (LDT * 2));
            }
            {
                int g = lane >> 3, r = lane & 7;
                int bn = wn * 32 + ((g >> 1) << 3) + r;
                int bk = ks * 16 + ((g & 1) << 3);
                uint32_t boff = base + TILE_B + (uint32_t)(bn * (LDT * 2) + bk * 2);
#pragma unroll
                for (int j = 0; j < 2; j++)
                    ldsm4(bh[j], boff + j * 16 * (LDT * 2));
            }
#pragma unroll
            for (int i = 0; i < 4; i++)
#pragma unroll
                for (int jj = 0; jj < 4; jj++)
                    mma16816(c[i][jj], a[i], &bh[jj >> 1][(jj & 1) * 2]);
        }
    }
    __syncthreads();

    float* eb = (float*)sm;
    float* red = (float*)(sm + 66560);
#pragma unroll
    for (int i = 0; i < 4; i++) {
#pragma unroll
        for (int jj = 0; jj < 4; jj++) {
            int r = wm * 64 + i * 16 + (lane >> 2);
            int cc = wn * 32 + jj * 8 + (lane & 3) * 2;
            *(float2*)&eb[r * 130 + cc]       = make_float2(c[i][jj][0], c[i][jj][1]);
            *(float2*)&eb[(r + 8) * 130 + cc] = make_float2(c[i][jj][2], c[i][jj][3]);
        }
    }
    __syncthreads();
    {
        int col = tid & 127, half = tid >> 7;
        float bias = g_b2p[col0 + col];
        float csum = 0.f;
        size_t gbase = (size_t)(row0 + half * 64) * Ee + col0 + col;
#pragma unroll 8
        for (int r = 0; r < 64; r++) {
            float v = ex2f(fmaxf(eb[(half * 64 + r) * 130 + col] + bias, 0.0f));
            csum += v;
            g_E[gbase + (size_t)r * Ee] = __float2half(v);
        }
        red[half * 128 + col] = csum;
    }
    __syncthreads();
    if (tid < 128)
        g_Zpart[(size_t)rt * Ee + col0 + tid] = red[tid] + red[128 + tid];
}

// ======================= K2b: softmax denominators (float4) =======================
__global__ void k_zreduce() {
    int idx4 = blockIdx.x * blockDim.x + threadIdx.x;   // 0..16383 (float4 index)
    int b = idx4 >> 11;                                 // 2048 float4 per batch
    int e4 = idx4 & 2047;
    float4 s = make_float4(0.f, 0.f, 0.f, 0.f);
#pragma unroll
    for (int i = 0; i < 8; i++) {
        float4 z = ((const float4*)g_Zpart)[(size_t)(b * 8 + i) * 2048 + e4];
        s.x += z.x; s.y += z.y; s.z += z.z; s.w += z.w;
    }
    ((float4*)g_Zinv)[idx4] = make_float4(1.f / s.x, 1.f / s.y, 1.f / s.z, 1.f / s.w);
}

// ======================= K3: syncless streaming pool (permuted E, RPC=2, 4-wide lanes) ==========
// E row is [p][d] (p = warp, d contiguous). Lane handles 4 chunks of 4 d values
// (16B per lane per vector op -> fully coalesced). Neighbors via shuffles only;
// zero smem, zero barriers. Grid 4096 kills the wave tail.
#define RPC 2
__global__ __launch_bounds__(512) void k_final(const float* __restrict__ x,
                                               float* __restrict__ out) {
    const unsigned FULL = 0xFFFFFFFFu;
    int tid = threadIdx.x, w = tid >> 5, lane = tid & 31;
    int b = blockIdx.x >> 9;                 // 512 CTAs per batch
    int row0 = blockIdx.x * RPC;

    float4 zr[4];
    {
        const float* Zb = g_Zinv + (size_t)b * Ee + w * Dd + lane * 4;
#pragma unroll
        for (int c = 0; c < 4; c++) zr[c] = *(const float4*)(Zb + c * 128);
    }

#pragma unroll
    for (int r = 0; r < RPC; r++) {
        int row = row0 + r;
        float xp = __ldg(&x[row * Pp + w]) * (1.0f / 3.0f);
        const __half* Eb = g_E + (size_t)row * Ee + w * Dd + lane * 4;

        float4 v[4];
#pragma unroll
        for (int c = 0; c < 4; c++) {
            uint2 ee = *(const uint2*)(Eb + c * 128);
            __half2 h0 = *(const __half2*)&ee.x;
            __half2 h1 = *(const __half2*)&ee.y;
            float2 f0 = __half22float2(h0), f1 = __half22float2(h1);
            v[c].x = f0.x * zr[c].x; v[c].y = f0.y * zr[c].y;
            v[c].z = f1.x * zr[c].z; v[c].w = f1.y * zr[c].w;
        }

        float lb[4], rb[4];
#pragma unroll
        for (int c = 0; c < 4; c++) {
            lb[c] = __shfl_up_sync(FULL, v[c].w, 1);
            rb[c] = __shfl_down_sync(FULL, v[c].x, 1);
        }
        // chunk-boundary fixes (lane0 left / lane31 right cross chunk edges)
        float t31_0 = __shfl_sync(FULL, v[0].w, 31);
        float t31_1 = __shfl_sync(FULL, v[1].w, 31);
        float t31_2 = __shfl_sync(FULL, v[2].w, 31);
        float t0_1  = __shfl_sync(FULL, v[1].x, 0);
        float t0_2  = __shfl_sync(FULL, v[2].x, 0);
        float t0_3  = __shfl_sync(FULL, v[3].x, 0);
        if (lane == 0)  { lb[0] = 0.0f; lb[1] = t31_0; lb[2] = t31_1; lb[3] = t31_2; }
        if (lane == 31) { rb[3] = 0.0f; rb[0] = t0_1;  rb[1] = t0_2;  rb[2] = t0_3; }

        size_t ob = ((size_t)row * Pp + w) * Dd + lane * 4;
#pragma unroll
        for (int c = 0; c < 4; c++) {
            float4 o;
            o.x = xp * (lb[c]  + v[c].x + v[c].y);
            o.y = xp * (v[c].x + v[c].y + v[c].z);
            o.z = xp * (v[c].y + v[c].z + v[c].w);
            o.w = xp * (v[c].z + v[c].w + rb[c]);
            *(float4*)(out + ob + c * 128) = o;
        }
    }
}

// ======================= launch =======================
extern "C" void kernel_launch(void* const* d_in, const int* in_sizes, int n_in,
                              void* d_out, int out_size) {
    const float* x  = (const float*)d_in[0];
    const float* W1 = (const float*)d_in[1];
    const float* b1 = (const float*)d_in[2];
    const float* W2 = (const float*)d_in[3];
    const float* b2 = (const float*)d_in[4];
    float* out = (float*)d_out;

    static int smem_set = 0;
    if (!smem_set) {
        cudaFuncSetAttribute(k_gemm_mma, cudaFuncAttributeMaxDynamicSharedMemorySize, SMEM_DYN);
        smem_set = 1;
    }

    k_prep<<<1536, 512>>>(x, W1, b1, W2, b2);
    k_gemm_mma<<<4096, 256, SMEM_DYN>>>();
    k_zreduce<<<64, 256>>>();
    k_final<<<Mm / RPC, 512>>>(x, out);
}